// round 5
// baseline (speedup 1.0000x reference)
#include <cuda_runtime.h>
#include <math.h>
#include <stdint.h>

#define Sdim 2048
#define Edim 512
#define WIN  11
#define Fdim (WIN * Edim)   // 5632
#define NTH  128
#define EH   256            // e-half width

// ---------------- smem layout (floats) ----------------
// xs2   : 2 planes * 11 rows * 256 e  float2 = 5632 float2 = 11264 floats
// red   : 4 warps * 22 float2                =   176 floats
// peer  : 22 float2                          =    44 floats
// gates : 22 float2                          =    44 floats
// mbar  : 8 bytes @ float offset 11528 (byte 46112, 8B aligned)
#define XS_F    0
#define RED_F   11264
#define PEER_F  11440
#define GATES_F 11484
#define MBAR_F  11528
#define SMEM_BYTES 46208

__device__ __forceinline__ uint32_t s2u(const void* p) {
    return (uint32_t)__cvta_generic_to_shared(p);
}
// Packed dual-fp32 FMA: a.{x,y} += {xlo,xhi} * w (broadcast)
__device__ __forceinline__ void ffma2(float2& a, float xlo, float xhi, float w) {
    asm("{\n\t.reg .b64 X, Wd, A;\n\t"
        "mov.b64 X, {%2, %3};\n\t"
        "mov.b64 Wd, {%4, %4};\n\t"
        "mov.b64 A, {%0, %1};\n\t"
        "fma.rn.f32x2 A, X, Wd, A;\n\t"
        "mov.b64 {%0, %1}, A;\n\t}"
        : "+f"(a.x), "+f"(a.y) : "f"(xlo), "f"(xhi), "f"(w));
}
// Packed dual-fp32 FMA, both packed
__device__ __forceinline__ void ffma2v(float2& a, float2 xv, float2 g) {
    asm("{\n\t.reg .b64 X, G, A;\n\t"
        "mov.b64 X, {%2, %3};\n\t"
        "mov.b64 G, {%4, %5};\n\t"
        "mov.b64 A, {%0, %1};\n\t"
        "fma.rn.f32x2 A, X, G, A;\n\t"
        "mov.b64 {%0, %1}, A;\n\t}"
        : "+f"(a.x), "+f"(a.y) : "f"(xv.x), "f"(xv.y), "f"(g.x), "f"(g.y));
}

extern __shared__ float smemf[];

__global__ __launch_bounds__(NTH, 4) __cluster_dims__(2, 1, 1)
void winattn_kernel(const float* __restrict__ x,
                    const float* __restrict__ W,
                    const float* __restrict__ bias,
                    float* __restrict__ out) {
    const int bid = blockIdx.x;
    const int s   = bid >> 2;
    const int b0  = ((bid >> 1) & 1) * 4;   // batch half: batches b0..b0+3
    const int tid = threadIdx.x;

    uint32_t rank;                           // == bid & 1 == e-half
    asm("mov.u32 %0, %%cluster_ctarank;" : "=r"(rank));
    const int e0 = (int)rank * EH;

    float2* xs2   = (float2*)(smemf + XS_F);     // [2][11][256] e-singles, (b even,b odd)
    float2* red   = (float2*)(smemf + RED_F);    // [4][22]
    float2* peer  = (float2*)(smemf + PEER_F);   // [22]
    float2* gates = (float2*)(smemf + GATES_F);  // [22]
    const uint32_t mb = s2u(smemf + MBAR_F);

    if (tid == 0)
        asm volatile("mbarrier.init.shared.b64 [%0], %1;" :: "r"(mb), "r"(22) : "memory");
    __syncthreads();
    asm volatile("barrier.cluster.arrive.aligned;" ::: "memory");
    asm volatile("barrier.cluster.wait.aligned;"   ::: "memory");

    // ---------------- Stage 1: stage x window (4 batches, e-half) ----------
    // tasks: (p in 0..1) x (w in 0..10) x (quad jq in 0..63) = 1408; 11 iters
    #pragma unroll
    for (int k = 0; k < 11; k++) {
        int i   = tid + NTH * k;
        int p   = i / 704;
        int rem = i - p * 704;
        int w   = rem >> 6;
        int e   = (rem & 63) << 2;        // 0..252, e within half
        int row = s + w - 5;
        float4 x0 = make_float4(0.f, 0.f, 0.f, 0.f);
        float4 x1 = make_float4(0.f, 0.f, 0.f, 0.f);
        if ((unsigned)row < (unsigned)Sdim) {
            const float* base = x + ((size_t)(b0 + 2 * p) * Sdim + row) * Edim + e0 + e;
            x0 = *(const float4*)base;
            x1 = *(const float4*)(base + (size_t)Sdim * Edim);
        }
        float4* dst = (float4*)xs2 + (size_t)p * 1408 + w * 128 + (e >> 1);
        dst[0] = make_float4(x0.x, x1.x, x0.y, x1.y);
        dst[1] = make_float4(x0.z, x1.z, x0.w, x1.w);
    }
    __syncthreads();

    // ---------------- Stage 2: partial gate dots over our e-half -----------
    float2 acc[2][WIN];
    #pragma unroll
    for (int p = 0; p < 2; p++)
        #pragma unroll
        for (int w = 0; w < WIN; w++)
            acc[p][w] = make_float2(0.f, 0.f);

    const float* Wt = W + (size_t)s * (WIN * Fdim) + e0 + 2 * tid;
    const float4* xsq = (const float4*)xs2;

    for (int i = 0; i < WIN; i++) {       // i = window row (feature chunk)
        float2 w2[WIN];
        #pragma unroll
        for (int w = 0; w < WIN; w++)
            w2[w] = *(const float2*)(Wt + (size_t)w * Fdim + i * Edim);

        float4 xq0 = xsq[            i * 128 + tid];
        float4 xq1 = xsq[1408 +      i * 128 + tid];

        #pragma unroll
        for (int w = 0; w < WIN; w++) {
            ffma2(acc[0][w], xq0.x, xq0.y, w2[w].x);
            ffma2(acc[0][w], xq0.z, xq0.w, w2[w].y);
            ffma2(acc[1][w], xq1.x, xq1.y, w2[w].x);
            ffma2(acc[1][w], xq1.z, xq1.w, w2[w].y);
        }
    }

    // ---------------- Stage 3: reduce + cluster exchange -> gates ----------
    float* af = (float*)acc;              // 44 floats
    #pragma unroll
    for (int off = 16; off > 0; off >>= 1) {
        #pragma unroll
        for (int i = 0; i < 44; i++)
            af[i] += __shfl_xor_sync(0xffffffffu, af[i], off);
    }
    const int lane = tid & 31, wrp = tid >> 5;
    if (lane == 0) {
        #pragma unroll
        for (int p = 0; p < 2; p++)
            #pragma unroll
            for (int w = 0; w < WIN; w++)
                red[wrp * 22 + p * WIN + w] = acc[p][w];
    }
    __syncthreads();

    if (tid < 22) {
        float2 t = make_float2(0.f, 0.f);
        #pragma unroll
        for (int q = 0; q < 4; q++) {
            float2 v = red[q * 22 + tid];
            t.x += v.x;
            t.y += v.y;
        }
        // send partial to peer CTA (other e-half)
        uint32_t paddr = s2u(peer + tid), raddr, rbar;
        uint32_t prank = rank ^ 1u;
        asm("mapa.shared::cluster.u32 %0, %1, %2;" : "=r"(raddr) : "r"(paddr), "r"(prank));
        asm("mapa.shared::cluster.u32 %0, %1, %2;" : "=r"(rbar)  : "r"(mb),    "r"(prank));
        uint64_t v64;
        asm("mov.b64 %0, {%1, %2};" : "=l"(v64) : "f"(t.x), "f"(t.y));
        asm volatile("st.shared::cluster.b64 [%0], %1;" :: "r"(raddr), "l"(v64) : "memory");
        asm volatile("mbarrier.arrive.release.cluster.shared::cluster.b64 _, [%0];"
                     :: "r"(rbar) : "memory");

        // wait for peer's 22 partials
        asm volatile(
            "{\n\t.reg .pred P;\n\t"
            "WAIT_%=:\n\t"
            "mbarrier.try_wait.parity.acquire.cluster.shared::cta.b64 P, [%0], 0, 0x989680;\n\t"
            "@P bra.uni DONE_%=;\n\t"
            "bra.uni WAIT_%=;\n\t"
            "DONE_%=:\n\t}"
            :: "r"(mb) : "memory");

        float2 pv = peer[tid];
        int p = tid / WIN;
        int w = tid - p * WIN;
        float bb = bias[s * WIN + w];
        float2 g;
        g.x = 1.0f / (1.0f + expf(-(t.x + pv.x + bb)));
        g.y = 1.0f / (1.0f + expf(-(t.y + pv.y + bb)));
        gates[tid] = g;
    }
    __syncthreads();

    // ---------------- Stage 4: score + tanh over our e-half ----------------
    #pragma unroll
    for (int p = 0; p < 2; p++) {
        float2 gw[WIN];
        #pragma unroll
        for (int w = 0; w < WIN; w++) gw[w] = gates[p * WIN + w];

        #pragma unroll
        for (int k = 0; k < 2; k++) {
            int j = tid + NTH * k;        // e-index within half, 0..255
            float2 a = make_float2(0.f, 0.f);
            #pragma unroll
            for (int w = 0; w < WIN; w++)
                ffma2v(a, xs2[(size_t)p * 2816 + w * 256 + j], gw[w]);
            size_t obase = ((size_t)(b0 + 2 * p) * Sdim + s) * Edim + e0 + j;
            out[obase]                       = tanhf(a.x);
            out[obase + (size_t)Sdim * Edim] = tanhf(a.y);
        }
    }
}

extern "C" void kernel_launch(void* const* d_in, const int* in_sizes, int n_in,
                              void* d_out, int out_size) {
    const float* x  = (const float*)d_in[0];
    const float* W  = (const float*)d_in[1];
    const float* bv = (const float*)d_in[2];
    float* out = (float*)d_out;

    cudaFuncSetAttribute(winattn_kernel,
                         cudaFuncAttributeMaxDynamicSharedMemorySize, SMEM_BYTES);
    winattn_kernel<<<4 * Sdim, NTH, SMEM_BYTES>>>(x, W, bv, out);
}

// round 8
// speedup vs baseline: 1.2406x; 1.2406x over previous
#include <cuda_runtime.h>
#include <math.h>

#define Sdim 2048
#define Edim 512
#define WIN  11
#define Fdim 5632            // WIN * Edim
#define NTH  128

// Packed dual-fp32 FMA: a.{x,y} += {xlo,xhi} * w   (w broadcast to both lanes)
__device__ __forceinline__ void ffma2(float2& a, float xlo, float xhi, float w) {
    asm("{\n\t.reg .b64 X, Wd, A;\n\t"
        "mov.b64 X, {%2, %3};\n\t"
        "mov.b64 Wd, {%4, %4};\n\t"
        "mov.b64 A, {%0, %1};\n\t"
        "fma.rn.f32x2 A, X, Wd, A;\n\t"
        "mov.b64 {%0, %1}, A;\n\t}"
        : "+f"(a.x), "+f"(a.y) : "f"(xlo), "f"(xhi), "f"(w));
}

__global__ __launch_bounds__(NTH, 4)
void winattn_kernel(const float* __restrict__ x,
                    const float* __restrict__ W,
                    const float* __restrict__ bias,
                    float* __restrict__ out) {
    __shared__ float2 red[4][22];      // per-warp partials (2 local pairs x 11 w)
    __shared__ float2 gates[22];       // gates for this CTA's 4 batches

    const int s   = blockIdx.x >> 1;
    const int b0  = (blockIdx.x & 1) * 4;   // batches b0..b0+3
    const int tid = threadIdx.x;
    const int ex  = 4 * tid;                // float4 slot within e (0..508)

    const size_t bst = (size_t)Sdim * Edim;
    const float* Wb = W + (size_t)s * (WIN * Fdim) + ex;
    const float* xb = x + (size_t)b0 * bst + ex;

    // ---------------- Stage A: full-f gate dots for 4 batches --------------
    float2 acc[2][WIN];                // pair p: (batch b0+2p, b0+2p+1)
    #pragma unroll
    for (int p = 0; p < 2; p++)
        #pragma unroll
        for (int w = 0; w < WIN; w++)
            acc[p][w] = make_float2(0.f, 0.f);

    for (int i = 0; i < WIN; i++) {    // window row = feature chunk
        int row = s + i - 5;
        if ((unsigned)row >= (unsigned)Sdim) continue;   // padded chunk: zero

        float4 w4[WIN];
        #pragma unroll
        for (int w = 0; w < WIN; w++)
            w4[w] = *(const float4*)(Wb + (size_t)w * Fdim + i * Edim);

        const float* xr = xb + (size_t)row * Edim;
        float4 xv[4];
        #pragma unroll
        for (int q = 0; q < 4; q++)
            xv[q] = *(const float4*)(xr + (size_t)q * bst);

        #pragma unroll
        for (int w = 0; w < WIN; w++) {
            ffma2(acc[0][w], xv[0].x, xv[1].x, w4[w].x);
            ffma2(acc[0][w], xv[0].y, xv[1].y, w4[w].y);
            ffma2(acc[0][w], xv[0].z, xv[1].z, w4[w].z);
            ffma2(acc[0][w], xv[0].w, xv[1].w, w4[w].w);
            ffma2(acc[1][w], xv[2].x, xv[3].x, w4[w].x);
            ffma2(acc[1][w], xv[2].y, xv[3].y, w4[w].y);
            ffma2(acc[1][w], xv[2].z, xv[3].z, w4[w].z);
            ffma2(acc[1][w], xv[2].w, xv[3].w, w4[w].w);
        }
    }

    // ---------------- reduce: warp shfl, then 4 warps via smem -------------
    float* af = (float*)acc;           // 44 floats
    #pragma unroll
    for (int off = 16; off > 0; off >>= 1) {
        #pragma unroll
        for (int i = 0; i < 44; i++)
            af[i] += __shfl_xor_sync(0xffffffffu, af[i], off);
    }
    const int lane = tid & 31, wrp = tid >> 5;
    if (lane == 0) {
        #pragma unroll
        for (int p = 0; p < 2; p++)
            #pragma unroll
            for (int w = 0; w < WIN; w++)
                red[wrp][p * WIN + w] = acc[p][w];
    }
    __syncthreads();

    if (tid < 22) {
        int p = tid / WIN;             // local pair 0..1
        int w = tid - p * WIN;
        float2 t = make_float2(0.f, 0.f);
        #pragma unroll
        for (int q = 0; q < 4; q++) {
            float2 v = red[q][tid];
            t.x += v.x;
            t.y += v.y;
        }
        float bb = bias[s * WIN + w];
        float2 gt;
        gt.x = 1.0f / (1.0f + expf(-(t.x + bb)));
        gt.y = 1.0f / (1.0f + expf(-(t.y + bb)));
        gates[tid] = gt;               // .x = batch b0+2p, .y = batch b0+2p+1
    }
    __syncthreads();

    // ---------------- Stage B: score + tanh (x via L2) ---------------------
    float2 a[4][2];                    // [local batch][lo/hi float2 of float4]
    #pragma unroll
    for (int q = 0; q < 4; q++) {
        a[q][0] = make_float2(0.f, 0.f);
        a[q][1] = make_float2(0.f, 0.f);
    }

    for (int w = 0; w < WIN; w++) {
        int row = s + w - 5;
        if ((unsigned)row >= (unsigned)Sdim) continue;
        const float* xr = xb + (size_t)row * Edim;
        #pragma unroll
        for (int q = 0; q < 4; q++) {
            float4 xv = *(const float4*)(xr + (size_t)q * bst);
            float2 gp = gates[(q >> 1) * WIN + w];
            float g = (q & 1) ? gp.y : gp.x;
            ffma2(a[q][0], xv.x, xv.y, g);
            ffma2(a[q][1], xv.z, xv.w, g);
        }
    }

    #pragma unroll
    for (int q = 0; q < 4; q++) {
        float4 o;
        o.x = tanhf(a[q][0].x);
        o.y = tanhf(a[q][0].y);
        o.z = tanhf(a[q][1].x);
        o.w = tanhf(a[q][1].y);
        *(float4*)(out + ((size_t)(b0 + q) * Sdim + s) * Edim + ex) = o;
    }
}

extern "C" void kernel_launch(void* const* d_in, const int* in_sizes, int n_in,
                              void* d_out, int out_size) {
    const float* x  = (const float*)d_in[0];
    const float* W  = (const float*)d_in[1];
    const float* bv = (const float*)d_in[2];
    float* out = (float*)d_out;

    winattn_kernel<<<2 * Sdim, NTH>>>(x, W, bv, out);
}

// round 9
// speedup vs baseline: 1.3166x; 1.0612x over previous
#include <cuda_runtime.h>
#include <math.h>

#define Sdim 2048
#define Edim 512
#define WIN  11
#define Fdim 5632            // WIN * Edim
#define NTH  128

// Packed dual-fp32 FMA: a.{x,y} += {xlo,xhi} * w   (w broadcast to both lanes)
__device__ __forceinline__ void ffma2(float2& a, float xlo, float xhi, float w) {
    asm("{\n\t.reg .b64 X, Wd, A;\n\t"
        "mov.b64 X, {%2, %3};\n\t"
        "mov.b64 Wd, {%4, %4};\n\t"
        "mov.b64 A, {%0, %1};\n\t"
        "fma.rn.f32x2 A, X, Wd, A;\n\t"
        "mov.b64 {%0, %1}, A;\n\t}"
        : "+f"(a.x), "+f"(a.y) : "f"(xlo), "f"(xhi), "f"(w));
}

__device__ __forceinline__ float tanh_fast(float v) {
    float r;
    asm("tanh.approx.f32 %0, %1;" : "=f"(r) : "f"(v));
    return r;
}

__device__ __forceinline__ void fma_block(float2 acc0[WIN], float2 acc1[WIN],
                                          const float4 w4[WIN],
                                          float4 xv0, float4 xv1, float4 xv2, float4 xv3) {
    #pragma unroll
    for (int w = 0; w < WIN; w++) {
        ffma2(acc0[w], xv0.x, xv1.x, w4[w].x);
        ffma2(acc0[w], xv0.y, xv1.y, w4[w].y);
        ffma2(acc0[w], xv0.z, xv1.z, w4[w].z);
        ffma2(acc0[w], xv0.w, xv1.w, w4[w].w);
        ffma2(acc1[w], xv2.x, xv3.x, w4[w].x);
        ffma2(acc1[w], xv2.y, xv3.y, w4[w].y);
        ffma2(acc1[w], xv2.z, xv3.z, w4[w].z);
        ffma2(acc1[w], xv2.w, xv3.w, w4[w].w);
    }
}

__global__ __launch_bounds__(NTH, 4)
void winattn_kernel(const float* __restrict__ x,
                    const float* __restrict__ W,
                    const float* __restrict__ bias,
                    float* __restrict__ out) {
    __shared__ float2 red[4][22];      // per-warp partials (2 local pairs x 11 w)
    __shared__ float2 gates[22];       // gates for this CTA's 4 batches

    const int s   = blockIdx.x >> 1;
    const int b0  = (blockIdx.x & 1) * 4;   // batches b0..b0+3
    const int tid = threadIdx.x;
    const int ex  = 4 * tid;                // float4 slot within e (0..508)

    const size_t bst = (size_t)Sdim * Edim;
    const float* Wb  = W + (size_t)s * (WIN * Fdim) + ex;
    const float* xb  = x + (size_t)b0 * bst + ex;
    const float* xr0 = xb + (size_t)(s - 5) * Edim;   // window start row (batch b0)
    const float* xr2 = xr0 + 2 * bst;                 // same row, batch b0+2
    const bool interior = (s >= 5) && (s <= Sdim - 6);

    // ---------------- Stage A: full-f gate dots for 4 batches --------------
    float2 acc[2][WIN];
    #pragma unroll
    for (int p = 0; p < 2; p++)
        #pragma unroll
        for (int w = 0; w < WIN; w++)
            acc[p][w] = make_float2(0.f, 0.f);

    if (interior) {
        #pragma unroll
        for (int i = 0; i < WIN; i++) {
            float4 w4[WIN];
            #pragma unroll
            for (int w = 0; w < WIN; w++)
                w4[w] = *(const float4*)(Wb + (size_t)w * Fdim + i * Edim);
            float4 xv0 = *(const float4*)(xr0 + i * Edim);
            float4 xv1 = *(const float4*)(xr0 + i * Edim + bst);
            float4 xv2 = *(const float4*)(xr2 + i * Edim);
            float4 xv3 = *(const float4*)(xr2 + i * Edim + bst);
            fma_block(acc[0], acc[1], w4, xv0, xv1, xv2, xv3);
        }
    } else {
        for (int i = 0; i < WIN; i++) {
            int row = s + i - 5;
            if ((unsigned)row >= (unsigned)Sdim) continue;
            float4 w4[WIN];
            #pragma unroll
            for (int w = 0; w < WIN; w++)
                w4[w] = *(const float4*)(Wb + (size_t)w * Fdim + i * Edim);
            const float* xr = xb + (size_t)row * Edim;
            float4 xv0 = *(const float4*)(xr);
            float4 xv1 = *(const float4*)(xr + bst);
            float4 xv2 = *(const float4*)(xr + 2 * bst);
            float4 xv3 = *(const float4*)(xr + 3 * bst);
            fma_block(acc[0], acc[1], w4, xv0, xv1, xv2, xv3);
        }
    }

    // ---------------- reduce: warp shfl, then 4 warps via smem -------------
    float* af = (float*)acc;           // 44 floats
    #pragma unroll
    for (int off = 16; off > 0; off >>= 1) {
        #pragma unroll
        for (int i = 0; i < 44; i++)
            af[i] += __shfl_xor_sync(0xffffffffu, af[i], off);
    }
    const int lane = tid & 31, wrp = tid >> 5;
    if (lane == 0) {
        #pragma unroll
        for (int p = 0; p < 2; p++)
            #pragma unroll
            for (int w = 0; w < WIN; w++)
                red[wrp][p * WIN + w] = acc[p][w];
    }
    __syncthreads();

    if (tid < 22) {
        int p = tid / WIN;             // local pair 0..1
        int w = tid - p * WIN;
        float2 t = make_float2(0.f, 0.f);
        #pragma unroll
        for (int q = 0; q < 4; q++) {
            float2 v = red[q][tid];
            t.x += v.x;
            t.y += v.y;
        }
        float bb = bias[s * WIN + w];
        float2 gt;
        gt.x = 1.0f / (1.0f + expf(-(t.x + bb)));
        gt.y = 1.0f / (1.0f + expf(-(t.y + bb)));
        gates[tid] = gt;               // .x = batch b0+2p, .y = batch b0+2p+1
    }
    __syncthreads();

    // ---------------- Stage B: score + tanh (x via L1/L2) ------------------
    float2 a[4][2];                    // [local batch][lo/hi float2 of float4]
    #pragma unroll
    for (int q = 0; q < 4; q++) {
        a[q][0] = make_float2(0.f, 0.f);
        a[q][1] = make_float2(0.f, 0.f);
    }

    if (interior) {
        #pragma unroll
        for (int w = 0; w < WIN; w++) {
            float4 xv0 = *(const float4*)(xr0 + w * Edim);
            float4 xv1 = *(const float4*)(xr0 + w * Edim + bst);
            float4 xv2 = *(const float4*)(xr2 + w * Edim);
            float4 xv3 = *(const float4*)(xr2 + w * Edim + bst);
            float2 g0 = gates[w];
            float2 g1 = gates[WIN + w];
            ffma2(a[0][0], xv0.x, xv0.y, g0.x);
            ffma2(a[0][1], xv0.z, xv0.w, g0.x);
            ffma2(a[1][0], xv1.x, xv1.y, g0.y);
            ffma2(a[1][1], xv1.z, xv1.w, g0.y);
            ffma2(a[2][0], xv2.x, xv2.y, g1.x);
            ffma2(a[2][1], xv2.z, xv2.w, g1.x);
            ffma2(a[3][0], xv3.x, xv3.y, g1.y);
            ffma2(a[3][1], xv3.z, xv3.w, g1.y);
        }
    } else {
        for (int w = 0; w < WIN; w++) {
            int row = s + w - 5;
            if ((unsigned)row >= (unsigned)Sdim) continue;
            const float* xr = xb + (size_t)row * Edim;
            #pragma unroll
            for (int q = 0; q < 4; q++) {
                float4 xv = *(const float4*)(xr + (size_t)q * bst);
                float2 gp = gates[(q >> 1) * WIN + w];
                float g = (q & 1) ? gp.y : gp.x;
                ffma2(a[q][0], xv.x, xv.y, g);
                ffma2(a[q][1], xv.z, xv.w, g);
            }
        }
    }

    #pragma unroll
    for (int q = 0; q < 4; q++) {
        float4 o;
        o.x = tanh_fast(a[q][0].x);
        o.y = tanh_fast(a[q][0].y);
        o.z = tanh_fast(a[q][1].x);
        o.w = tanh_fast(a[q][1].y);
        *(float4*)(out + ((size_t)(b0 + q) * Sdim + s) * Edim + ex) = o;
    }
}

extern "C" void kernel_launch(void* const* d_in, const int* in_sizes, int n_in,
                              void* d_out, int out_size) {
    const float* x  = (const float*)d_in[0];
    const float* W  = (const float*)d_in[1];
    const float* bv = (const float*)d_in[2];
    float* out = (float*)d_out;

    winattn_kernel<<<2 * Sdim, NTH>>>(x, W, bv, out);
}